// round 13
// baseline (speedup 1.0000x reference)
#include <cuda_runtime.h>
#include <math_constants.h>

// ChamferLoss B=8, N=8192, D=3 — R13: R10 structure (direct per-warp g_row
// writes, no smem combine) with QB=4 register diet to reach occ 8
// (8 warps/SMSP). Inner unit (2 preds x 1 gt): 3 fma2 + 1 add2 + 4 FMNMX.

#define NPTS   8192
#define BATCH  8
#define TPB    128
#define RP     4                          // pred pairs per lane (8 preds)
#define REFS_PER_BLOCK (TPB * RP * 2)     // 1024
#define PT     (NPTS / REFS_PER_BLOCK)    // 8 pred tiles
#define QS     16                         // gt slices
#define QPER   (NPTS / QS)                // 512 gts per block
#define QB     4                          // gt batch (fold granularity)
#define NWARP  (TPB / 32)                 // 4
#define FLATN  (BATCH * NPTS)             // 65536

__device__ float g_row[PT * NWARP][FLATN];   // 32 slices of per-gt row mins
__device__ float g_col[QS][FLATN];           // 16 slices of per-pred col mins

typedef unsigned long long ull;

union P2 {
    ull    u;
    float2 f;
};

struct __align__(16) QPack { ull x, y, z, n; };

__device__ __forceinline__ ull pack2(float a, float b) {
    P2 p; p.f = make_float2(a, b); return p.u;
}
__device__ __forceinline__ ull fma2(ull a, ull b, ull c) {
    ull r; asm("fma.rn.f32x2 %0, %1, %2, %3;" : "=l"(r) : "l"(a), "l"(b), "l"(c)); return r;
}
__device__ __forceinline__ ull add2(ull a, ull b) {
    ull r; asm("add.rn.f32x2 %0, %1, %2;" : "=l"(r) : "l"(a), "l"(b)); return r;
}

__global__ __launch_bounds__(TPB, 8)
void chamfer_fused_kernel(const float* __restrict__ preds,
                          const float* __restrict__ gts,
                          float* __restrict__ out) {
    __shared__ QPack qbuf[QPER];   // 16KB

    if (blockIdx.x == 0 && blockIdx.y == 0 && blockIdx.z == 0 &&
        threadIdx.x == 0) {
        out[0] = 0.0f;   // only the later reduce kernel touches out
    }

    const int pt  = blockIdx.x;
    const int b   = blockIdx.y;
    const int s   = blockIdx.z;
    const int tid = threadIdx.x;
    const int w   = tid >> 5;
    const int L   = tid & 31;

    // ---- this lane's 8 preds in registers (4 packed pairs) ----
    ull rx2[RP], ry2[RP], rz2[RP], rn2[RP];
    float colL[RP], colH[RP];
    const int refbase = pt * REFS_PER_BLOCK + w * (RP * 64) + L * 2;
    #pragma unroll
    for (int r = 0; r < RP; r++) {
        const int idx = refbase + r * 64;
        const float* rp = preds + ((size_t)b * NPTS + idx) * 3;
        const float2 v0 = *(const float2*)(rp + 0);
        const float2 v1 = *(const float2*)(rp + 2);
        const float2 v2 = *(const float2*)(rp + 4);
        rx2[r] = pack2(v0.x, v1.y);
        ry2[r] = pack2(v0.y, v2.x);
        rz2[r] = pack2(v1.x, v2.y);
        rn2[r] = pack2(v0.x * v0.x + v0.y * v0.y + v1.x * v1.x,
                       v1.y * v1.y + v2.x * v2.x + v2.y * v2.y);
        colL[r] = CUDART_INF_F;
        colH[r] = CUDART_INF_F;
    }

    // ---- stage gt slice in shared: duplicated, prescaled -2, packed norm ----
    for (int q = tid; q < QPER; q += TPB) {
        const float* gp = gts + ((size_t)b * NPTS + s * QPER + q) * 3;
        const float gx = gp[0], gy = gp[1], gz = gp[2];
        QPack pk;
        pk.x = pack2(-2.0f * gx, -2.0f * gx);
        pk.y = pack2(-2.0f * gy, -2.0f * gy);
        pk.z = pack2(-2.0f * gz, -2.0f * gz);
        const float gn = gx * gx + gy * gy + gz * gz;
        pk.n = pack2(gn, gn);
        qbuf[q] = pk;
    }
    __syncthreads();

    float* growp = &g_row[pt * NWARP + w][(size_t)b * NPTS + s * QPER];

    for (int qb = 0; qb < QPER; qb += QB) {
        float rowloc[QB];
        #pragma unroll
        for (int qq = 0; qq < QB; qq++) {
            const ulonglong2 pxy = *(const ulonglong2*)(&qbuf[qb + qq].x);
            const ulonglong2 pzn = *(const ulonglong2*)(&qbuf[qb + qq].z);
            float ra = CUDART_INF_F, rb = CUDART_INF_F;
            #pragma unroll
            for (int r = 0; r < RP; r++) {
                P2 t;
                t.u = fma2(pzn.x, rz2[r], rn2[r]);
                t.u = fma2(pxy.y, ry2[r], t.u);
                t.u = fma2(pxy.x, rx2[r], t.u);    // ||p||^2 - 2<g,p>, 2 preds
                ra = fminf(ra, t.f.x);
                rb = fminf(rb, t.f.y);
                P2 u;
                u.u = add2(t.u, pzn.y);            // + ||g||^2 -> full distance
                colL[r] = fminf(colL[r], u.f.x);
                colH[r] = fminf(colH[r], u.f.y);
            }
            rowloc[qq] = fminf(ra, rb);
        }

        // ---- fold-shuffle: reduce 4 per-lane values across 32 lanes ----
        #pragma unroll
        for (int k = 0; k < 2; k++) {
            const float sent = (L & 16) ? rowloc[k] : rowloc[k + 2];
            const float recv = __shfl_xor_sync(0xffffffffu, sent, 16);
            const float keep = (L & 16) ? rowloc[k + 2] : rowloc[k];
            rowloc[k] = fminf(keep, recv);
        }
        {
            const float sent = (L & 8) ? rowloc[0] : rowloc[1];
            const float recv = __shfl_xor_sync(0xffffffffu, sent, 8);
            const float keep = (L & 8) ? rowloc[1] : rowloc[0];
            rowloc[0] = fminf(keep, recv);
        }
        rowloc[0] = fminf(rowloc[0], __shfl_xor_sync(0xffffffffu, rowloc[0], 4));
        rowloc[0] = fminf(rowloc[0], __shfl_xor_sync(0xffffffffu, rowloc[0], 2));
        rowloc[0] = fminf(rowloc[0], __shfl_xor_sync(0xffffffffu, rowloc[0], 1));

        const int qi = qb + (((L >> 4) & 1) << 1) + ((L >> 3) & 1);
        if ((L & 7) == 0) growp[qi] = rowloc[0];
    }

    // ---- write col-min partials for this gt slice ----
    #pragma unroll
    for (int r = 0; r < RP; r++) {
        const int idx = refbase + r * 64;
        float2 v; v.x = colL[r]; v.y = colH[r];
        *(float2*)(&g_col[s][(size_t)b * NPTS + idx]) = v;
    }
}

__global__ __launch_bounds__(256)
void chamfer_reduce_kernel(const float* __restrict__ gts,
                           float* __restrict__ out) {
    __shared__ float sred[256];
    const int idx = blockIdx.x * 256 + threadIdx.x;   // 0 .. 2*FLATN-1

    float v;
    if (idx < FLATN) {
        v = g_col[0][idx];
        #pragma unroll
        for (int s = 1; s < QS; s++) v = fminf(v, g_col[s][idx]);
    } else {
        const int g = idx - FLATN;
        v = g_row[0][g];
        #pragma unroll
        for (int k = 1; k < PT * NWARP; k++) v = fminf(v, g_row[k][g]);
        const float* gp = gts + (size_t)g * 3;
        v += gp[0] * gp[0] + gp[1] * gp[1] + gp[2] * gp[2];
    }

    sred[threadIdx.x] = v;
    __syncthreads();
    #pragma unroll
    for (int sft = 128; sft > 32; sft >>= 1) {
        if (threadIdx.x < sft) sred[threadIdx.x] += sred[threadIdx.x + sft];
        __syncthreads();
    }
    if (threadIdx.x < 32) {
        float r = sred[threadIdx.x] + sred[threadIdx.x + 32];
        #pragma unroll
        for (int o = 16; o > 0; o >>= 1)
            r += __shfl_down_sync(0xffffffffu, r, o);
        if (threadIdx.x == 0) atomicAdd(out, r);
    }
}

extern "C" void kernel_launch(void* const* d_in, const int* in_sizes, int n_in,
                              void* d_out, int out_size) {
    const float* preds = (const float*)d_in[0];
    const float* gts   = (const float*)d_in[1];
    float* out = (float*)d_out;

    dim3 grid(PT, BATCH, QS);   // (8, 8, 16) = 1024 blocks, occ 8 -> one wave
    chamfer_fused_kernel<<<grid, TPB>>>(preds, gts, out);

    chamfer_reduce_kernel<<<(2 * FLATN) / 256, 256>>>(gts, out);
}

// round 14
// speedup vs baseline: 1.0231x; 1.0231x over previous
#include <cuda_runtime.h>
#include <math_constants.h>

// ChamferLoss B=8, N=8192, D=3 — R14: R10 compute core (occ 7, RP=4, QB=8) +
// zero-init-safe atomicMin partials: key = int(0x80000000 ^ bits(u)) is the
// signed-int view of -u (u>=0): strictly negative, monotone in u, so signed
// atomicMin with a zero-initialized buffer is correct. Reduce kernel decodes,
// sums, and resets buffers to 0 for the next graph replay.

#define NPTS   8192
#define BATCH  8
#define TPB    128
#define RP     4                          // pred pairs per lane (8 preds)
#define REFS_PER_BLOCK (TPB * RP * 2)     // 1024
#define PT     (NPTS / REFS_PER_BLOCK)    // 8 pred tiles
#define QS     16                         // gt slices
#define QPER   (NPTS / QS)                // 512 gts per block
#define QB     8                          // gt batch (fold granularity)
#define FLATN  (BATCH * NPTS)             // 65536

__device__ int g_best_col[FLATN];   // zero-init; holds key(min_u) per pred
__device__ int g_best_row[FLATN];   // zero-init; holds key(min_u) per gt

typedef unsigned long long ull;

union P2 {
    ull    u;
    float2 f;
};

struct __align__(16) QPack { ull x, y, z, n; };

__device__ __forceinline__ ull pack2(float a, float b) {
    P2 p; p.f = make_float2(a, b); return p.u;
}
__device__ __forceinline__ ull fma2(ull a, ull b, ull c) {
    ull r; asm("fma.rn.f32x2 %0, %1, %2, %3;" : "=l"(r) : "l"(a), "l"(b), "l"(c)); return r;
}
__device__ __forceinline__ ull add2(ull a, ull b) {
    ull r; asm("add.rn.f32x2 %0, %1, %2;" : "=l"(r) : "l"(a), "l"(b)); return r;
}
__device__ __forceinline__ int minkey(float u) {
    return (int)(0x80000000u ^ __float_as_uint(u));
}

__global__ __launch_bounds__(TPB, 7)
void chamfer_fused_kernel(const float* __restrict__ preds,
                          const float* __restrict__ gts,
                          float* __restrict__ out) {
    __shared__ QPack qbuf[QPER];   // 16KB

    if (blockIdx.x == 0 && blockIdx.y == 0 && blockIdx.z == 0 &&
        threadIdx.x == 0) {
        out[0] = 0.0f;   // only the later reduce kernel touches out
    }

    const int pt  = blockIdx.x;
    const int b   = blockIdx.y;
    const int s   = blockIdx.z;
    const int tid = threadIdx.x;
    const int w   = tid >> 5;
    const int L   = tid & 31;

    // ---- this lane's 8 preds in registers (4 packed pairs) ----
    ull rx2[RP], ry2[RP], rz2[RP], rn2[RP];
    float colL[RP], colH[RP];
    const int refbase = pt * REFS_PER_BLOCK + w * (RP * 64) + L * 2;
    #pragma unroll
    for (int r = 0; r < RP; r++) {
        const int idx = refbase + r * 64;
        const float* rp = preds + ((size_t)b * NPTS + idx) * 3;
        const float2 v0 = *(const float2*)(rp + 0);
        const float2 v1 = *(const float2*)(rp + 2);
        const float2 v2 = *(const float2*)(rp + 4);
        rx2[r] = pack2(v0.x, v1.y);
        ry2[r] = pack2(v0.y, v2.x);
        rz2[r] = pack2(v1.x, v2.y);
        rn2[r] = pack2(v0.x * v0.x + v0.y * v0.y + v1.x * v1.x,
                       v1.y * v1.y + v2.x * v2.x + v2.y * v2.y);
        colL[r] = CUDART_INF_F;
        colH[r] = CUDART_INF_F;
    }

    // ---- stage gt slice in shared: duplicated, prescaled -2, packed norm ----
    for (int q = tid; q < QPER; q += TPB) {
        const float* gp = gts + ((size_t)b * NPTS + s * QPER + q) * 3;
        const float gx = gp[0], gy = gp[1], gz = gp[2];
        QPack pk;
        pk.x = pack2(-2.0f * gx, -2.0f * gx);
        pk.y = pack2(-2.0f * gy, -2.0f * gy);
        pk.z = pack2(-2.0f * gz, -2.0f * gz);
        const float gn = gx * gx + gy * gy + gz * gz;
        pk.n = pack2(gn, gn);
        qbuf[q] = pk;
    }
    __syncthreads();

    int* growp = &g_best_row[(size_t)b * NPTS + s * QPER];

    for (int qb = 0; qb < QPER; qb += QB) {
        float rowloc[QB];
        #pragma unroll
        for (int qq = 0; qq < QB; qq++) {
            const ulonglong2 pxy = *(const ulonglong2*)(&qbuf[qb + qq].x);
            const ulonglong2 pzn = *(const ulonglong2*)(&qbuf[qb + qq].z);
            float ra = CUDART_INF_F, rb = CUDART_INF_F;
            #pragma unroll
            for (int r = 0; r < RP; r++) {
                P2 t;
                t.u = fma2(pzn.x, rz2[r], rn2[r]);
                t.u = fma2(pxy.y, ry2[r], t.u);
                t.u = fma2(pxy.x, rx2[r], t.u);    // ||p||^2 - 2<g,p>, 2 preds
                P2 u;
                u.u = add2(t.u, pzn.y);            // + ||g||^2 -> full distance
                ra = fminf(ra, u.f.x);
                rb = fminf(rb, u.f.y);
                colL[r] = fminf(colL[r], u.f.x);
                colH[r] = fminf(colH[r], u.f.y);
            }
            rowloc[qq] = fminf(ra, rb);
        }

        // ---- fold-shuffle: reduce 8 per-lane values across 32 lanes ----
        #pragma unroll
        for (int k = 0; k < 4; k++) {
            const float sent = (L & 16) ? rowloc[k] : rowloc[k + 4];
            const float recv = __shfl_xor_sync(0xffffffffu, sent, 16);
            const float keep = (L & 16) ? rowloc[k + 4] : rowloc[k];
            rowloc[k] = fminf(keep, recv);
        }
        #pragma unroll
        for (int k = 0; k < 2; k++) {
            const float sent = (L & 8) ? rowloc[k] : rowloc[k + 2];
            const float recv = __shfl_xor_sync(0xffffffffu, sent, 8);
            const float keep = (L & 8) ? rowloc[k + 2] : rowloc[k];
            rowloc[k] = fminf(keep, recv);
        }
        {
            const float sent = (L & 4) ? rowloc[0] : rowloc[1];
            const float recv = __shfl_xor_sync(0xffffffffu, sent, 4);
            const float keep = (L & 4) ? rowloc[1] : rowloc[0];
            rowloc[0] = fminf(keep, recv);
        }
        rowloc[0] = fminf(rowloc[0], __shfl_xor_sync(0xffffffffu, rowloc[0], 2));
        rowloc[0] = fminf(rowloc[0], __shfl_xor_sync(0xffffffffu, rowloc[0], 1));

        const int qi = qb + (((L >> 4) & 1) << 2) + (((L >> 3) & 1) << 1) +
                       ((L >> 2) & 1);
        if ((L & 3) == 0) atomicMin(&growp[qi], minkey(rowloc[0]));
    }

    // ---- col-min partials via atomicMin ----
    #pragma unroll
    for (int r = 0; r < RP; r++) {
        const int idx = refbase + r * 64;
        atomicMin(&g_best_col[(size_t)b * NPTS + idx],     minkey(colL[r]));
        atomicMin(&g_best_col[(size_t)b * NPTS + idx + 1], minkey(colH[r]));
    }
}

__global__ __launch_bounds__(256)
void chamfer_reduce_kernel(float* __restrict__ out) {
    __shared__ float sred[256];
    const int idx = blockIdx.x * 256 + threadIdx.x;   // 0 .. 2*FLATN-1

    int key;
    if (idx < FLATN) {
        key = g_best_col[idx];
        g_best_col[idx] = 0;     // reset for next graph replay
    } else {
        key = g_best_row[idx - FLATN];
        g_best_row[idx - FLATN] = 0;
    }
    const float v = __uint_as_float(0x80000000u ^ (unsigned)key);

    sred[threadIdx.x] = v;
    __syncthreads();
    #pragma unroll
    for (int sft = 128; sft > 32; sft >>= 1) {
        if (threadIdx.x < sft) sred[threadIdx.x] += sred[threadIdx.x + sft];
        __syncthreads();
    }
    if (threadIdx.x < 32) {
        float r = sred[threadIdx.x] + sred[threadIdx.x + 32];
        #pragma unroll
        for (int o = 16; o > 0; o >>= 1)
            r += __shfl_down_sync(0xffffffffu, r, o);
        if (threadIdx.x == 0) atomicAdd(out, r);
    }
}

extern "C" void kernel_launch(void* const* d_in, const int* in_sizes, int n_in,
                              void* d_out, int out_size) {
    const float* preds = (const float*)d_in[0];
    const float* gts   = (const float*)d_in[1];
    float* out = (float*)d_out;

    dim3 grid(PT, BATCH, QS);   // (8, 8, 16) = 1024 blocks, occ 7 -> one wave
    chamfer_fused_kernel<<<grid, TPB>>>(preds, gts, out);

    chamfer_reduce_kernel<<<(2 * FLATN) / 256, 256>>>(out);
}

// round 15
// speedup vs baseline: 1.1205x; 1.0951x over previous
#include <cuda_runtime.h>
#include <math_constants.h>

// ChamferLoss B=8, N=8192, D=3 — R15: R10 compute kernel VERBATIM (occ 7,
// RP=4, QB=8, per-warp g_row slices) + MLP-optimized reduce kernel:
// each thread reduces 4 adjacent indices with float4 loads (coalesced,
// 16-32 independent loads in flight) instead of 1 index with serial loads.

#define NPTS   8192
#define BATCH  8
#define TPB    128
#define RP     4                          // pred pairs per lane (8 preds)
#define REFS_PER_BLOCK (TPB * RP * 2)     // 1024
#define PT     (NPTS / REFS_PER_BLOCK)    // 8 pred tiles
#define QS     16                         // gt slices
#define QPER   (NPTS / QS)                // 512 gts per block
#define QB     8                          // gt batch (fold granularity)
#define NWARP  (TPB / 32)                 // 4
#define FLATN  (BATCH * NPTS)             // 65536
#define RSLICE (PT * NWARP)               // 32 row slices

__device__ float g_row[RSLICE][FLATN];    // per-warp pred-slice row mins
__device__ float g_col[QS][FLATN];        // per-gt-slice col mins

typedef unsigned long long ull;

union P2 {
    ull    u;
    float2 f;
};

struct __align__(16) QPack { ull x, y, z, n; };

__device__ __forceinline__ ull pack2(float a, float b) {
    P2 p; p.f = make_float2(a, b); return p.u;
}
__device__ __forceinline__ ull fma2(ull a, ull b, ull c) {
    ull r; asm("fma.rn.f32x2 %0, %1, %2, %3;" : "=l"(r) : "l"(a), "l"(b), "l"(c)); return r;
}
__device__ __forceinline__ ull add2(ull a, ull b) {
    ull r; asm("add.rn.f32x2 %0, %1, %2;" : "=l"(r) : "l"(a), "l"(b)); return r;
}

__global__ __launch_bounds__(TPB, 7)
void chamfer_fused_kernel(const float* __restrict__ preds,
                          const float* __restrict__ gts,
                          float* __restrict__ out) {
    __shared__ QPack qbuf[QPER];   // 16KB

    if (blockIdx.x == 0 && blockIdx.y == 0 && blockIdx.z == 0 &&
        threadIdx.x == 0) {
        out[0] = 0.0f;   // only the later reduce kernel touches out
    }

    const int pt  = blockIdx.x;
    const int b   = blockIdx.y;
    const int s   = blockIdx.z;
    const int tid = threadIdx.x;
    const int w   = tid >> 5;
    const int L   = tid & 31;

    // ---- this lane's 8 preds in registers (4 packed pairs) ----
    ull rx2[RP], ry2[RP], rz2[RP], rn2[RP];
    float colL[RP], colH[RP];
    const int refbase = pt * REFS_PER_BLOCK + w * (RP * 64) + L * 2;
    #pragma unroll
    for (int r = 0; r < RP; r++) {
        const int idx = refbase + r * 64;
        const float* rp = preds + ((size_t)b * NPTS + idx) * 3;
        const float2 v0 = *(const float2*)(rp + 0);
        const float2 v1 = *(const float2*)(rp + 2);
        const float2 v2 = *(const float2*)(rp + 4);
        rx2[r] = pack2(v0.x, v1.y);
        ry2[r] = pack2(v0.y, v2.x);
        rz2[r] = pack2(v1.x, v2.y);
        rn2[r] = pack2(v0.x * v0.x + v0.y * v0.y + v1.x * v1.x,
                       v1.y * v1.y + v2.x * v2.x + v2.y * v2.y);
        colL[r] = CUDART_INF_F;
        colH[r] = CUDART_INF_F;
    }

    // ---- stage gt slice in shared: duplicated, prescaled -2, packed norm ----
    for (int q = tid; q < QPER; q += TPB) {
        const float* gp = gts + ((size_t)b * NPTS + s * QPER + q) * 3;
        const float gx = gp[0], gy = gp[1], gz = gp[2];
        QPack pk;
        pk.x = pack2(-2.0f * gx, -2.0f * gx);
        pk.y = pack2(-2.0f * gy, -2.0f * gy);
        pk.z = pack2(-2.0f * gz, -2.0f * gz);
        const float gn = gx * gx + gy * gy + gz * gz;
        pk.n = pack2(gn, gn);
        qbuf[q] = pk;
    }
    __syncthreads();

    float* growp = &g_row[pt * NWARP + w][(size_t)b * NPTS + s * QPER];

    for (int qb = 0; qb < QPER; qb += QB) {
        float rowloc[QB];
        #pragma unroll
        for (int qq = 0; qq < QB; qq++) {
            const ulonglong2 pxy = *(const ulonglong2*)(&qbuf[qb + qq].x);
            const ulonglong2 pzn = *(const ulonglong2*)(&qbuf[qb + qq].z);
            float ra = CUDART_INF_F, rb = CUDART_INF_F;
            #pragma unroll
            for (int r = 0; r < RP; r++) {
                P2 t;
                t.u = fma2(pzn.x, rz2[r], rn2[r]);
                t.u = fma2(pxy.y, ry2[r], t.u);
                t.u = fma2(pxy.x, rx2[r], t.u);    // ||p||^2 - 2<g,p>, 2 preds
                ra = fminf(ra, t.f.x);
                rb = fminf(rb, t.f.y);
                P2 u;
                u.u = add2(t.u, pzn.y);            // + ||g||^2 -> full distance
                colL[r] = fminf(colL[r], u.f.x);
                colH[r] = fminf(colH[r], u.f.y);
            }
            rowloc[qq] = fminf(ra, rb);
        }

        // ---- fold-shuffle: reduce 8 per-lane values across 32 lanes ----
        #pragma unroll
        for (int k = 0; k < 4; k++) {
            const float sent = (L & 16) ? rowloc[k] : rowloc[k + 4];
            const float recv = __shfl_xor_sync(0xffffffffu, sent, 16);
            const float keep = (L & 16) ? rowloc[k + 4] : rowloc[k];
            rowloc[k] = fminf(keep, recv);
        }
        #pragma unroll
        for (int k = 0; k < 2; k++) {
            const float sent = (L & 8) ? rowloc[k] : rowloc[k + 2];
            const float recv = __shfl_xor_sync(0xffffffffu, sent, 8);
            const float keep = (L & 8) ? rowloc[k + 2] : rowloc[k];
            rowloc[k] = fminf(keep, recv);
        }
        {
            const float sent = (L & 4) ? rowloc[0] : rowloc[1];
            const float recv = __shfl_xor_sync(0xffffffffu, sent, 4);
            const float keep = (L & 4) ? rowloc[1] : rowloc[0];
            rowloc[0] = fminf(keep, recv);
        }
        rowloc[0] = fminf(rowloc[0], __shfl_xor_sync(0xffffffffu, rowloc[0], 2));
        rowloc[0] = fminf(rowloc[0], __shfl_xor_sync(0xffffffffu, rowloc[0], 1));

        const int qi = qb + (((L >> 4) & 1) << 2) + (((L >> 3) & 1) << 1) +
                       ((L >> 2) & 1);
        if ((L & 3) == 0) growp[qi] = rowloc[0];
    }

    // ---- write col-min partials for this gt slice ----
    #pragma unroll
    for (int r = 0; r < RP; r++) {
        const int idx = refbase + r * 64;
        float2 v; v.x = colL[r]; v.y = colH[r];
        *(float2*)(&g_col[s][(size_t)b * NPTS + idx]) = v;
    }
}

__device__ __forceinline__ float4 min4(float4 a, float4 b) {
    return make_float4(fminf(a.x, b.x), fminf(a.y, b.y),
                       fminf(a.z, b.z), fminf(a.w, b.w));
}

// One thread reduces 4 adjacent indices via float4 loads (high MLP).
// Threads [0, FLATN/4): col side. Threads [FLATN/4, 2*FLATN/4): row side.
__global__ __launch_bounds__(256)
void chamfer_reduce_kernel(const float* __restrict__ gts,
                           float* __restrict__ out) {
    __shared__ float sred[256];
    const int t = blockIdx.x * 256 + threadIdx.x;   // 0 .. FLATN/2 - 1

    float4 v;
    if (t < FLATN / 4) {
        const int i4 = t * 4;
        v = *(const float4*)(&g_col[0][i4]);
        #pragma unroll
        for (int s = 1; s < QS; s++)
            v = min4(v, *(const float4*)(&g_col[s][i4]));
    } else {
        const int i4 = (t - FLATN / 4) * 4;   // gt flat index base
        v = *(const float4*)(&g_row[0][i4]);
        #pragma unroll
        for (int k = 1; k < RSLICE; k++)
            v = min4(v, *(const float4*)(&g_row[k][i4]));
        // add ||g||^2 for each of the 4 gts (12 contiguous floats)
        const float4 a = *(const float4*)(gts + (size_t)i4 * 3 + 0);
        const float4 bq = *(const float4*)(gts + (size_t)i4 * 3 + 4);
        const float4 c = *(const float4*)(gts + (size_t)i4 * 3 + 8);
        v.x += a.x * a.x + a.y * a.y + a.z * a.z;
        v.y += a.w * a.w + bq.x * bq.x + bq.y * bq.y;
        v.z += bq.z * bq.z + bq.w * bq.w + c.x * c.x;
        v.w += c.y * c.y + c.z * c.z + c.w * c.w;
    }
    const float sum = (v.x + v.y) + (v.z + v.w);

    sred[threadIdx.x] = sum;
    __syncthreads();
    #pragma unroll
    for (int sft = 128; sft > 32; sft >>= 1) {
        if (threadIdx.x < sft) sred[threadIdx.x] += sred[threadIdx.x + sft];
        __syncthreads();
    }
    if (threadIdx.x < 32) {
        float r = sred[threadIdx.x] + sred[threadIdx.x + 32];
        #pragma unroll
        for (int o = 16; o > 0; o >>= 1)
            r += __shfl_down_sync(0xffffffffu, r, o);
        if (threadIdx.x == 0) atomicAdd(out, r);
    }
}

extern "C" void kernel_launch(void* const* d_in, const int* in_sizes, int n_in,
                              void* d_out, int out_size) {
    const float* preds = (const float*)d_in[0];
    const float* gts   = (const float*)d_in[1];
    float* out = (float*)d_out;

    dim3 grid(PT, BATCH, QS);   // (8, 8, 16) = 1024 blocks, occ 7 -> one wave
    chamfer_fused_kernel<<<grid, TPB>>>(preds, gts, out);

    // FLATN/2 threads: each reduces 4 indices (col half + row half).
    chamfer_reduce_kernel<<<(FLATN / 2) / 256, 256>>>(gts, out);
}

// round 16
// speedup vs baseline: 1.1299x; 1.0084x over previous
#include <cuda_runtime.h>
#include <math_constants.h>

// ChamferLoss B=8, N=8192, D=3 — R16: R10 compute kernel VERBATIM + reduce v3:
// slice dimension split across lanes (col: 2 lanes/col x 8 slices; row: 4
// lanes/col x 8 slices), partial min4 combined via warp shuffles. 384 blocks,
// MLP 8 per thread -> bandwidth-bound (~2-3us) instead of latency-bound.

#define NPTS   8192
#define BATCH  8
#define TPB    128
#define RP     4                          // pred pairs per lane (8 preds)
#define REFS_PER_BLOCK (TPB * RP * 2)     // 1024
#define PT     (NPTS / REFS_PER_BLOCK)    // 8 pred tiles
#define QS     16                         // gt slices
#define QPER   (NPTS / QS)                // 512 gts per block
#define QB     8                          // gt batch (fold granularity)
#define NWARP  (TPB / 32)                 // 4
#define FLATN  (BATCH * NPTS)             // 65536
#define RSLICE (PT * NWARP)               // 32 row slices
#define NCOL4  (FLATN / 4)                // 16384 float4 columns

__device__ float g_row[RSLICE][FLATN];    // per-warp pred-slice row mins
__device__ float g_col[QS][FLATN];        // per-gt-slice col mins

typedef unsigned long long ull;

union P2 {
    ull    u;
    float2 f;
};

struct __align__(16) QPack { ull x, y, z, n; };

__device__ __forceinline__ ull pack2(float a, float b) {
    P2 p; p.f = make_float2(a, b); return p.u;
}
__device__ __forceinline__ ull fma2(ull a, ull b, ull c) {
    ull r; asm("fma.rn.f32x2 %0, %1, %2, %3;" : "=l"(r) : "l"(a), "l"(b), "l"(c)); return r;
}
__device__ __forceinline__ ull add2(ull a, ull b) {
    ull r; asm("add.rn.f32x2 %0, %1, %2;" : "=l"(r) : "l"(a), "l"(b)); return r;
}

__global__ __launch_bounds__(TPB, 7)
void chamfer_fused_kernel(const float* __restrict__ preds,
                          const float* __restrict__ gts,
                          float* __restrict__ out) {
    __shared__ QPack qbuf[QPER];   // 16KB

    if (blockIdx.x == 0 && blockIdx.y == 0 && blockIdx.z == 0 &&
        threadIdx.x == 0) {
        out[0] = 0.0f;   // only the later reduce kernel touches out
    }

    const int pt  = blockIdx.x;
    const int b   = blockIdx.y;
    const int s   = blockIdx.z;
    const int tid = threadIdx.x;
    const int w   = tid >> 5;
    const int L   = tid & 31;

    // ---- this lane's 8 preds in registers (4 packed pairs) ----
    ull rx2[RP], ry2[RP], rz2[RP], rn2[RP];
    float colL[RP], colH[RP];
    const int refbase = pt * REFS_PER_BLOCK + w * (RP * 64) + L * 2;
    #pragma unroll
    for (int r = 0; r < RP; r++) {
        const int idx = refbase + r * 64;
        const float* rp = preds + ((size_t)b * NPTS + idx) * 3;
        const float2 v0 = *(const float2*)(rp + 0);
        const float2 v1 = *(const float2*)(rp + 2);
        const float2 v2 = *(const float2*)(rp + 4);
        rx2[r] = pack2(v0.x, v1.y);
        ry2[r] = pack2(v0.y, v2.x);
        rz2[r] = pack2(v1.x, v2.y);
        rn2[r] = pack2(v0.x * v0.x + v0.y * v0.y + v1.x * v1.x,
                       v1.y * v1.y + v2.x * v2.x + v2.y * v2.y);
        colL[r] = CUDART_INF_F;
        colH[r] = CUDART_INF_F;
    }

    // ---- stage gt slice in shared: duplicated, prescaled -2, packed norm ----
    for (int q = tid; q < QPER; q += TPB) {
        const float* gp = gts + ((size_t)b * NPTS + s * QPER + q) * 3;
        const float gx = gp[0], gy = gp[1], gz = gp[2];
        QPack pk;
        pk.x = pack2(-2.0f * gx, -2.0f * gx);
        pk.y = pack2(-2.0f * gy, -2.0f * gy);
        pk.z = pack2(-2.0f * gz, -2.0f * gz);
        const float gn = gx * gx + gy * gy + gz * gz;
        pk.n = pack2(gn, gn);
        qbuf[q] = pk;
    }
    __syncthreads();

    float* growp = &g_row[pt * NWARP + w][(size_t)b * NPTS + s * QPER];

    for (int qb = 0; qb < QPER; qb += QB) {
        float rowloc[QB];
        #pragma unroll
        for (int qq = 0; qq < QB; qq++) {
            const ulonglong2 pxy = *(const ulonglong2*)(&qbuf[qb + qq].x);
            const ulonglong2 pzn = *(const ulonglong2*)(&qbuf[qb + qq].z);
            float ra = CUDART_INF_F, rb = CUDART_INF_F;
            #pragma unroll
            for (int r = 0; r < RP; r++) {
                P2 t;
                t.u = fma2(pzn.x, rz2[r], rn2[r]);
                t.u = fma2(pxy.y, ry2[r], t.u);
                t.u = fma2(pxy.x, rx2[r], t.u);    // ||p||^2 - 2<g,p>, 2 preds
                ra = fminf(ra, t.f.x);
                rb = fminf(rb, t.f.y);
                P2 u;
                u.u = add2(t.u, pzn.y);            // + ||g||^2 -> full distance
                colL[r] = fminf(colL[r], u.f.x);
                colH[r] = fminf(colH[r], u.f.y);
            }
            rowloc[qq] = fminf(ra, rb);
        }

        // ---- fold-shuffle: reduce 8 per-lane values across 32 lanes ----
        #pragma unroll
        for (int k = 0; k < 4; k++) {
            const float sent = (L & 16) ? rowloc[k] : rowloc[k + 4];
            const float recv = __shfl_xor_sync(0xffffffffu, sent, 16);
            const float keep = (L & 16) ? rowloc[k + 4] : rowloc[k];
            rowloc[k] = fminf(keep, recv);
        }
        #pragma unroll
        for (int k = 0; k < 2; k++) {
            const float sent = (L & 8) ? rowloc[k] : rowloc[k + 2];
            const float recv = __shfl_xor_sync(0xffffffffu, sent, 8);
            const float keep = (L & 8) ? rowloc[k + 2] : rowloc[k];
            rowloc[k] = fminf(keep, recv);
        }
        {
            const float sent = (L & 4) ? rowloc[0] : rowloc[1];
            const float recv = __shfl_xor_sync(0xffffffffu, sent, 4);
            const float keep = (L & 4) ? rowloc[1] : rowloc[0];
            rowloc[0] = fminf(keep, recv);
        }
        rowloc[0] = fminf(rowloc[0], __shfl_xor_sync(0xffffffffu, rowloc[0], 2));
        rowloc[0] = fminf(rowloc[0], __shfl_xor_sync(0xffffffffu, rowloc[0], 1));

        const int qi = qb + (((L >> 4) & 1) << 2) + (((L >> 3) & 1) << 1) +
                       ((L >> 2) & 1);
        if ((L & 3) == 0) growp[qi] = rowloc[0];
    }

    // ---- write col-min partials for this gt slice ----
    #pragma unroll
    for (int r = 0; r < RP; r++) {
        const int idx = refbase + r * 64;
        float2 v; v.x = colL[r]; v.y = colH[r];
        *(float2*)(&g_col[s][(size_t)b * NPTS + idx]) = v;
    }
}

__device__ __forceinline__ float4 min4(float4 a, float4 b) {
    return make_float4(fminf(a.x, b.x), fminf(a.y, b.y),
                       fminf(a.z, b.z), fminf(a.w, b.w));
}
__device__ __forceinline__ float4 shfl_min4(float4 v, int mask) {
    float4 o;
    o.x = __shfl_xor_sync(0xffffffffu, v.x, mask);
    o.y = __shfl_xor_sync(0xffffffffu, v.y, mask);
    o.z = __shfl_xor_sync(0xffffffffu, v.z, mask);
    o.w = __shfl_xor_sync(0xffffffffu, v.w, mask);
    return min4(v, o);
}

// Reduce v3: slice dim split across lanes.
//   threads [0, 2*NCOL4):      col side, 2 lanes/column x 8 slices
//   threads [2*NCOL4, 6*NCOL4): row side, 4 lanes/column x 8 slices
__global__ __launch_bounds__(256)
void chamfer_reduce_kernel(const float* __restrict__ gts,
                           float* __restrict__ out) {
    __shared__ float sred[256];
    const int t = blockIdx.x * 256 + threadIdx.x;
    const int L = threadIdx.x & 31;
    float sum = 0.0f;

    if (t < 2 * NCOL4) {
        // col side: warp covers 16 columns x 2 slice-halves
        const int c    = (t >> 5) * 16 + (L & 15);
        const int part = L >> 4;                 // 0 or 1
        const int i4   = c * 4;
        float4 v = *(const float4*)(&g_col[part * 8][i4]);
        #pragma unroll
        for (int s = 1; s < 8; s++)
            v = min4(v, *(const float4*)(&g_col[part * 8 + s][i4]));
        v = shfl_min4(v, 16);
        if (L < 16) sum = (v.x + v.y) + (v.z + v.w);
    } else {
        // row side: warp covers 8 columns x 4 slice-quarters
        const int tr   = t - 2 * NCOL4;
        const int c    = (tr >> 5) * 8 + (L & 7);
        const int part = L >> 3;                 // 0..3
        const int i4   = c * 4;
        float4 v = *(const float4*)(&g_row[part * 8][i4]);
        #pragma unroll
        for (int k = 1; k < 8; k++)
            v = min4(v, *(const float4*)(&g_row[part * 8 + k][i4]));
        v = shfl_min4(v, 8);
        v = shfl_min4(v, 16);
        if (L < 8) {
            // add ||g||^2 for the 4 gts of this column (12 contiguous floats)
            const float4 a  = *(const float4*)(gts + (size_t)i4 * 3 + 0);
            const float4 bq = *(const float4*)(gts + (size_t)i4 * 3 + 4);
            const float4 cc = *(const float4*)(gts + (size_t)i4 * 3 + 8);
            v.x += a.x * a.x + a.y * a.y + a.z * a.z;
            v.y += a.w * a.w + bq.x * bq.x + bq.y * bq.y;
            v.z += bq.z * bq.z + bq.w * bq.w + cc.x * cc.x;
            v.w += cc.y * cc.y + cc.z * cc.z + cc.w * cc.w;
            sum = (v.x + v.y) + (v.z + v.w);
        }
    }

    sred[threadIdx.x] = sum;
    __syncthreads();
    #pragma unroll
    for (int sft = 128; sft > 32; sft >>= 1) {
        if (threadIdx.x < sft) sred[threadIdx.x] += sred[threadIdx.x + sft];
        __syncthreads();
    }
    if (threadIdx.x < 32) {
        float r = sred[threadIdx.x] + sred[threadIdx.x + 32];
        #pragma unroll
        for (int o = 16; o > 0; o >>= 1)
            r += __shfl_down_sync(0xffffffffu, r, o);
        if (threadIdx.x == 0) atomicAdd(out, r);
    }
}

extern "C" void kernel_launch(void* const* d_in, const int* in_sizes, int n_in,
                              void* d_out, int out_size) {
    const float* preds = (const float*)d_in[0];
    const float* gts   = (const float*)d_in[1];
    float* out = (float*)d_out;

    dim3 grid(PT, BATCH, QS);   // (8, 8, 16) = 1024 blocks, occ 7 -> one wave
    chamfer_fused_kernel<<<grid, TPB>>>(preds, gts, out);

    // 6*NCOL4 threads = 98304 -> 384 blocks of 256
    chamfer_reduce_kernel<<<(6 * NCOL4) / 256, 256>>>(gts, out);
}